// round 15
// baseline (speedup 1.0000x reference)
#include <cuda_runtime.h>
#include <cuda_bf16.h>
#include <cstdint>

#define BATCH 8
#define CIN 256
#define COUT 128
#define HIN 60
#define WIN 80
#define HUP 122
#define HOUT 120
#define WOUT 160
#define NPIX (HOUT*WOUT)   // 19200

// ---------------------------------------------------------------------------
// Device-global scratch
// ---------------------------------------------------------------------------
__device__ __align__(16) uint32_t      g_dwp[(size_t)BATCH * CIN * NPIX]; // packed bf16 (hi<<16)|lo
__device__ __align__(16) __nv_bfloat16 g_Ah[COUT * CIN];                  // pw hi [o][c]
__device__ __align__(16) __nv_bfloat16 g_Al[COUT * CIN];                  // pw lo [o][c]

// ---------------------------------------------------------------------------
// Kernel: split pointwise weights [o][c] fp32 -> bf16 hi/lo
// ---------------------------------------------------------------------------
__global__ void pwsplit_kernel(const float* __restrict__ pw) {
    int i = blockIdx.x * 256 + threadIdx.x;
    float v = pw[i];
    __nv_bfloat16 h = __float2bfloat16(v);
    __nv_bfloat16 l = __float2bfloat16(v - __bfloat162float(h));
    g_Ah[i] = h;
    g_Al[i] = l;
}

// ---------------------------------------------------------------------------
// Kernel: bilinear upsample + 3x3 depthwise — R14 row-blocked structure,
// store packs bf16 hi/lo into one uint32 per pixel.
// ---------------------------------------------------------------------------
__device__ __forceinline__ void hlerp10(const float* __restrict__ vr,
                                        const int* __restrict__ x0c,
                                        const float* __restrict__ fxc,
                                        float (&uu)[10]) {
#pragma unroll
    for (int j = 0; j < 10; j++) {
        int x0 = x0c[j];
        int x1 = x0 + 1; if (x1 > WIN - 1) x1 = WIN - 1;
        float a  = vr[x0];
        float b2 = vr[x1];
        uu[j] = a + fxc[j] * (b2 - a);
    }
}

__device__ __forceinline__ void conv8p(const float (&a)[10], const float (&b)[10],
                                       const float (&c)[10], const float* kd,
                                       uint32_t* __restrict__ dst) {
    uint32_t rp[8];
#pragma unroll
    for (int ww = 0; ww < 8; ww++) {
        float acc = 0.0f;
#pragma unroll
        for (int j = 0; j < 3; j++) acc = fmaf(kd[j],     a[ww + j], acc);
#pragma unroll
        for (int j = 0; j < 3; j++) acc = fmaf(kd[3 + j], b[ww + j], acc);
#pragma unroll
        for (int j = 0; j < 3; j++) acc = fmaf(kd[6 + j], c[ww + j], acc);
        __nv_bfloat16 hh = __float2bfloat16(acc);
        __nv_bfloat16 ll = __float2bfloat16(acc - __bfloat162float(hh));
        rp[ww] = ((uint32_t)__bfloat16_as_ushort(hh) << 16) |
                  (uint32_t)__bfloat16_as_ushort(ll);
    }
    uint4* d4 = (uint4*)dst;
    d4[0] = make_uint4(rp[0], rp[1], rp[2], rp[3]);
    d4[1] = make_uint4(rp[4], rp[5], rp[6], rp[7]);
}

__global__ __launch_bounds__(256) void dw_kernel(const float* __restrict__ x,
                                                 const float* __restrict__ wdw) {
    __shared__ float vs[HUP * WIN];                  // 39040 B

    int bc = blockIdx.x;
    int c  = bc & (CIN - 1);
    const float* xp = x + (size_t)bc * (HIN * WIN);
    uint32_t* op = g_dwp + (size_t)bc * NPIX;
    int tid = threadIdx.x;

    const float SY = (float)(59.0 / 121.0);
    const float SX = (float)(79.0 / 161.0);

    for (int i = tid; i < HUP * WIN; i += 256) {
        int rr = i / WIN;
        int xc = i - rr * WIN;
        float hy  = rr * SY;
        float y0f = floorf(hy);
        int   y0  = (int)y0f;
        float fy  = hy - y0f;
        int   y1  = y0 + 1; if (y1 > HIN - 1) y1 = HIN - 1;
        float a  = xp[y0 * WIN + xc];
        float b2 = xp[y1 * WIN + xc];
        vs[i] = a + fy * (b2 - a);
    }

    float kd[9];
#pragma unroll
    for (int t = 0; t < 9; t++) kd[t] = __ldg(wdw + c * 9 + t);

    __syncthreads();

    // 600 items = 30 row-groups (4 out rows) x 20 col-strips
    for (int s = tid; s < 600; s += 256) {
        int hg = s / 20;
        int w0 = (s - hg * 20) * 8;
        int h0 = hg * 4;

        int   x0c[10];
        float fxc[10];
#pragma unroll
        for (int j = 0; j < 10; j++) {
            int   cc  = w0 + j;
            float wx  = cc * SX;
            float x0f = floorf(wx);
            x0c[j] = (int)x0f;
            fxc[j] = wx - x0f;
        }

        float u0[10], u1[10], u2[10];
        hlerp10(vs + (h0 + 0) * WIN, x0c, fxc, u0);
        hlerp10(vs + (h0 + 1) * WIN, x0c, fxc, u1);

        hlerp10(vs + (h0 + 2) * WIN, x0c, fxc, u2);
        conv8p(u0, u1, u2, kd, op + (h0 + 0) * WOUT + w0);

        hlerp10(vs + (h0 + 3) * WIN, x0c, fxc, u0);
        conv8p(u1, u2, u0, kd, op + (h0 + 1) * WOUT + w0);

        hlerp10(vs + (h0 + 4) * WIN, x0c, fxc, u1);
        conv8p(u2, u0, u1, kd, op + (h0 + 2) * WOUT + w0);

        hlerp10(vs + (h0 + 5) * WIN, x0c, fxc, u2);
        conv8p(u0, u1, u2, kd, op + (h0 + 3) * WOUT + w0);
    }
}

// ---------------------------------------------------------------------------
// GEMM via mma.sync split-bf16 3-pass — R6 skeleton; B loader is a raw
// uint4 copy (packed from dw); B fragments via LDS.32 + PRMT.
// ---------------------------------------------------------------------------
#define APAD 40      // A smem row stride (bf16 elems)
#define BPADu 132    // B smem row stride (u32 words): conflict-free loads

__device__ __forceinline__ void mma_bf16(float* d, const uint32_t* a, const uint32_t* b) {
    asm volatile(
        "mma.sync.aligned.m16n8k16.row.col.f32.bf16.bf16.f32 "
        "{%0,%1,%2,%3}, {%4,%5,%6,%7}, {%8,%9}, {%0,%1,%2,%3};"
        : "+f"(d[0]), "+f"(d[1]), "+f"(d[2]), "+f"(d[3])
        : "r"(a[0]), "r"(a[1]), "r"(a[2]), "r"(a[3]), "r"(b[0]), "r"(b[1]));
}

__global__ __launch_bounds__(256) void gemm_kernel(float* __restrict__ out) {
    __shared__ __nv_bfloat16 Ash[128 * APAD];        // 10240 B
    __shared__ __nv_bfloat16 Als[128 * APAD];        // 10240 B
    __shared__ uint32_t      Bps[32 * BPADu];        // 16896 B   (37376 total)

    int tid  = threadIdx.x;
    int lane = tid & 31;
    int wid  = tid >> 5;

    int b  = blockIdx.x / (NPIX / 128);
    int p0 = (blockIdx.x - b * (NPIX / 128)) * 128;

    const uint32_t* dwp = g_dwp + (size_t)b * CIN * NPIX + p0;

    int mw = (wid >> 2) * 64;
    int nw = (wid & 3) * 32;
    int g  = lane >> 2;
    int q  = lane & 3;

    float acc[4][4][4];
#pragma unroll
    for (int i = 0; i < 4; i++)
#pragma unroll
        for (int j = 0; j < 4; j++)
#pragma unroll
            for (int k = 0; k < 4; k++) acc[i][j][k] = 0.0f;

    for (int ck = 0; ck < CIN / 32; ++ck) {
        __syncthreads();

        // --- load A chunk [128 o][32 k] bf16 hi+lo (coalesced 16B) ---
#pragma unroll
        for (int i = 0; i < 2; i++) {
            int idx = tid + i * 256;
            int o = idx >> 2, qq = idx & 3;
            size_t goff = (size_t)o * 512 + (size_t)ck * 64 + qq * 16;
            uint4 vh = *(const uint4*)((const char*)g_Ah + goff);
            uint4 vl = *(const uint4*)((const char*)g_Al + goff);
            *(uint4*)((char*)Ash + o * (APAD * 2) + qq * 16) = vh;
            *(uint4*)((char*)Als + o * (APAD * 2) + qq * 16) = vl;
        }

        // --- load B chunk [32 c][128 p] packed u32: raw copy, no conversion ---
#pragma unroll
        for (int i = 0; i < 4; i++) {
            int idx = tid + i * 256;
            int c  = idx >> 5;
            int p4 = (idx & 31) * 4;
            uint4 v = *(const uint4*)(dwp + (size_t)(ck * 32 + c) * NPIX + p4);
            *(uint4*)&Bps[c * BPADu + p4] = v;
        }
        __syncthreads();

        // --- compute: 2 k16 steps per chunk ---
#pragma unroll
        for (int kk = 0; kk < 32; kk += 16) {
            int k0 = kk + q * 2;

            // B fragments: packed word -> PRMT split into hi/lo bf16x2
            uint32_t bh[4][2], bl[4][2];
#pragma unroll
            for (int nt = 0; nt < 4; nt++) {
                int n = nw + nt * 8 + g;
                uint32_t w0 = Bps[k0 * BPADu + n];
                uint32_t w1 = Bps[(k0 + 1) * BPADu + n];
                bh[nt][0] = __byte_perm(w0, w1, 0x7632);
                bl[nt][0] = __byte_perm(w0, w1, 0x5410);
                uint32_t w2 = Bps[(k0 + 8) * BPADu + n];
                uint32_t w3 = Bps[(k0 + 9) * BPADu + n];
                bh[nt][1] = __byte_perm(w2, w3, 0x7632);
                bl[nt][1] = __byte_perm(w2, w3, 0x5410);
            }

            uint32_t ah[4][4];
#pragma unroll
            for (int mt = 0; mt < 4; mt++) {
                int m = mw + mt * 16 + g;
                ah[mt][0] = *(const uint32_t*)&Ash[m * APAD + k0];
                ah[mt][1] = *(const uint32_t*)&Ash[(m + 8) * APAD + k0];
                ah[mt][2] = *(const uint32_t*)&Ash[m * APAD + k0 + 8];
                ah[mt][3] = *(const uint32_t*)&Ash[(m + 8) * APAD + k0 + 8];
            }

#pragma unroll
            for (int mt = 0; mt < 4; mt++)
#pragma unroll
                for (int nt = 0; nt < 4; nt++)
                    mma_bf16(acc[mt][nt], ah[mt], bh[nt]);

            uint32_t al[4][4];
#pragma unroll
            for (int mt = 0; mt < 4; mt++) {
                int m = mw + mt * 16 + g;
                al[mt][0] = *(const uint32_t*)&Als[m * APAD + k0];
                al[mt][1] = *(const uint32_t*)&Als[(m + 8) * APAD + k0];
                al[mt][2] = *(const uint32_t*)&Als[m * APAD + k0 + 8];
                al[mt][3] = *(const uint32_t*)&Als[(m + 8) * APAD + k0 + 8];
            }
#pragma unroll
            for (int mt = 0; mt < 4; mt++)
#pragma unroll
                for (int nt = 0; nt < 4; nt++)
                    mma_bf16(acc[mt][nt], al[mt], bh[nt]);

#pragma unroll
            for (int mt = 0; mt < 4; mt++)
#pragma unroll
                for (int nt = 0; nt < 4; nt++)
                    mma_bf16(acc[mt][nt], ah[mt], bl[nt]);
        }
    }

    // --- epilogue ---
    float* base = out + (size_t)b * COUT * NPIX + p0;
#pragma unroll
    for (int mt = 0; mt < 4; mt++) {
#pragma unroll
        for (int nt = 0; nt < 4; nt++) {
            int m = mw + mt * 16 + g;
            int n = nw + nt * 8 + q * 2;
            *(float2*)&base[(size_t)m * NPIX + n] =
                make_float2(acc[mt][nt][0], acc[mt][nt][1]);
            *(float2*)&base[(size_t)(m + 8) * NPIX + n] =
                make_float2(acc[mt][nt][2], acc[mt][nt][3]);
        }
    }
}

// ---------------------------------------------------------------------------
// Launch (monolithic, single stream)
// ---------------------------------------------------------------------------
extern "C" void kernel_launch(void* const* d_in, const int* in_sizes, int n_in,
                              void* d_out, int out_size) {
    const float* x   = (const float*)d_in[0];   // [8,256,60,80]
    const float* wdw = (const float*)d_in[1];   // [256,1,3,3]
    const float* wpw = (const float*)d_in[2];   // [128,256]
    float* out = (float*)d_out;                 // [8,128,120,160]

    pwsplit_kernel<<<128, 256>>>(wpw);
    dw_kernel<<<BATCH * CIN, 256>>>(x, wdw);
    gemm_kernel<<<BATCH * (NPIX / 128), 256>>>(out);
}

// round 16
// speedup vs baseline: 1.1697x; 1.1697x over previous
#include <cuda_runtime.h>
#include <cuda_bf16.h>
#include <cstdint>

#define BATCH 8
#define CIN 256
#define COUT 128
#define HIN 60
#define WIN 80
#define HUP 122
#define HOUT 120
#define WOUT 160
#define NPIX (HOUT*WOUT)   // 19200

// ---------------------------------------------------------------------------
// Device-global scratch
// ---------------------------------------------------------------------------
__device__ __align__(16) float         g_dw[(size_t)BATCH * CIN * NPIX]; // [b][c][p]
__device__ __align__(16) __nv_bfloat16 g_Ah[COUT * CIN];                 // pw hi [o][c]
__device__ __align__(16) __nv_bfloat16 g_Al[COUT * CIN];                 // pw lo [o][c]

// packed bf16x2 convert: returns (bf16(hi)<<16) | bf16(lo)
__device__ __forceinline__ uint32_t bf16x2_rn(float hi, float lo) {
    uint32_t r;
    asm("cvt.rn.bf16x2.f32 %0, %1, %2;" : "=r"(r) : "f"(hi), "f"(lo));
    return r;
}

// ---------------------------------------------------------------------------
// Kernel: split pointwise weights [o][c] fp32 -> bf16 hi/lo
// ---------------------------------------------------------------------------
__global__ void pwsplit_kernel(const float* __restrict__ pw) {
    int i = blockIdx.x * 256 + threadIdx.x;
    float v = pw[i];
    __nv_bfloat16 h = __float2bfloat16(v);
    __nv_bfloat16 l = __float2bfloat16(v - __bfloat162float(h));
    g_Ah[i] = h;
    g_Al[i] = l;
}

// ---------------------------------------------------------------------------
// Kernel: bilinear upsample + 3x3 depthwise — EXACT R14 version.
// ---------------------------------------------------------------------------
__device__ __forceinline__ void hlerp10(const float* __restrict__ vr,
                                        const int* __restrict__ x0c,
                                        const float* __restrict__ fxc,
                                        float (&uu)[10]) {
#pragma unroll
    for (int j = 0; j < 10; j++) {
        int x0 = x0c[j];
        int x1 = x0 + 1; if (x1 > WIN - 1) x1 = WIN - 1;
        float a  = vr[x0];
        float b2 = vr[x1];
        uu[j] = a + fxc[j] * (b2 - a);
    }
}

__device__ __forceinline__ void conv8(const float (&a)[10], const float (&b)[10],
                                      const float (&c)[10], const float* kd,
                                      float* __restrict__ dst) {
    float res[8];
#pragma unroll
    for (int ww = 0; ww < 8; ww++) {
        float acc = 0.0f;
#pragma unroll
        for (int j = 0; j < 3; j++) acc = fmaf(kd[j],     a[ww + j], acc);
#pragma unroll
        for (int j = 0; j < 3; j++) acc = fmaf(kd[3 + j], b[ww + j], acc);
#pragma unroll
        for (int j = 0; j < 3; j++) acc = fmaf(kd[6 + j], c[ww + j], acc);
        res[ww] = acc;
    }
    float4* d4 = (float4*)dst;
    d4[0] = make_float4(res[0], res[1], res[2], res[3]);
    d4[1] = make_float4(res[4], res[5], res[6], res[7]);
}

__global__ __launch_bounds__(256) void dw_kernel(const float* __restrict__ x,
                                                 const float* __restrict__ wdw) {
    __shared__ float vs[HUP * WIN];                  // 39040 B

    int bc = blockIdx.x;
    int c  = bc & (CIN - 1);
    const float* xp = x + (size_t)bc * (HIN * WIN);
    float* op = g_dw + (size_t)bc * NPIX;
    int tid = threadIdx.x;

    const float SY = (float)(59.0 / 121.0);
    const float SX = (float)(79.0 / 161.0);

    for (int i = tid; i < HUP * WIN; i += 256) {
        int rr = i / WIN;
        int xc = i - rr * WIN;
        float hy  = rr * SY;
        float y0f = floorf(hy);
        int   y0  = (int)y0f;
        float fy  = hy - y0f;
        int   y1  = y0 + 1; if (y1 > HIN - 1) y1 = HIN - 1;
        float a  = xp[y0 * WIN + xc];
        float b2 = xp[y1 * WIN + xc];
        vs[i] = a + fy * (b2 - a);
    }

    float kd[9];
#pragma unroll
    for (int t = 0; t < 9; t++) kd[t] = __ldg(wdw + c * 9 + t);

    __syncthreads();

    // 600 items = 30 row-groups (4 out rows) x 20 col-strips
    for (int s = tid; s < 600; s += 256) {
        int hg = s / 20;
        int w0 = (s - hg * 20) * 8;
        int h0 = hg * 4;

        int   x0c[10];
        float fxc[10];
#pragma unroll
        for (int j = 0; j < 10; j++) {
            int   cc  = w0 + j;
            float wx  = cc * SX;
            float x0f = floorf(wx);
            x0c[j] = (int)x0f;
            fxc[j] = wx - x0f;
        }

        float u0[10], u1[10], u2[10];
        hlerp10(vs + (h0 + 0) * WIN, x0c, fxc, u0);
        hlerp10(vs + (h0 + 1) * WIN, x0c, fxc, u1);

        hlerp10(vs + (h0 + 2) * WIN, x0c, fxc, u2);
        conv8(u0, u1, u2, kd, op + (h0 + 0) * WOUT + w0);

        hlerp10(vs + (h0 + 3) * WIN, x0c, fxc, u0);
        conv8(u1, u2, u0, kd, op + (h0 + 1) * WOUT + w0);

        hlerp10(vs + (h0 + 4) * WIN, x0c, fxc, u1);
        conv8(u2, u0, u1, kd, op + (h0 + 2) * WOUT + w0);

        hlerp10(vs + (h0 + 5) * WIN, x0c, fxc, u2);
        conv8(u0, u1, u2, kd, op + (h0 + 3) * WOUT + w0);
    }
}

// ---------------------------------------------------------------------------
// GEMM via mma.sync split-bf16 3-pass — R6/R14 skeleton; only the B
// conversion uses cvt.rn.bf16x2.f32 (packed output, ~45% fewer loader ops).
// ---------------------------------------------------------------------------
#define APAD 40
#define BPAD 136

__device__ __forceinline__ void mma_bf16(float* d, const uint32_t* a, const uint32_t* b) {
    asm volatile(
        "mma.sync.aligned.m16n8k16.row.col.f32.bf16.bf16.f32 "
        "{%0,%1,%2,%3}, {%4,%5,%6,%7}, {%8,%9}, {%0,%1,%2,%3};"
        : "+f"(d[0]), "+f"(d[1]), "+f"(d[2]), "+f"(d[3])
        : "r"(a[0]), "r"(a[1]), "r"(a[2]), "r"(a[3]), "r"(b[0]), "r"(b[1]));
}

__global__ __launch_bounds__(256) void gemm_kernel(float* __restrict__ out) {
    __shared__ __nv_bfloat16 Ash[128 * APAD];
    __shared__ __nv_bfloat16 Als[128 * APAD];
    __shared__ unsigned short Bhs[32 * BPAD];
    __shared__ unsigned short Bls[32 * BPAD];

    int tid  = threadIdx.x;
    int lane = tid & 31;
    int wid  = tid >> 5;

    int b  = blockIdx.x / (NPIX / 128);
    int p0 = (blockIdx.x - b * (NPIX / 128)) * 128;

    const float* dwp = g_dw + (size_t)b * CIN * NPIX + p0;

    int mw = (wid >> 2) * 64;
    int nw = (wid & 3) * 32;
    int g  = lane >> 2;
    int q  = lane & 3;

    float acc[4][4][4];
#pragma unroll
    for (int i = 0; i < 4; i++)
#pragma unroll
        for (int j = 0; j < 4; j++)
#pragma unroll
            for (int k = 0; k < 4; k++) acc[i][j][k] = 0.0f;

    for (int ck = 0; ck < CIN / 32; ++ck) {
        __syncthreads();

        // --- load A chunk [128 o][32 k] bf16 hi+lo (coalesced 16B) ---
#pragma unroll
        for (int i = 0; i < 2; i++) {
            int idx = tid + i * 256;
            int o = idx >> 2, qq = idx & 3;
            size_t goff = (size_t)o * 512 + (size_t)ck * 64 + qq * 16;
            uint4 vh = *(const uint4*)((const char*)g_Ah + goff);
            uint4 vl = *(const uint4*)((const char*)g_Al + goff);
            *(uint4*)((char*)Ash + o * (APAD * 2) + qq * 16) = vh;
            *(uint4*)((char*)Als + o * (APAD * 2) + qq * 16) = vl;
        }

        // --- load B chunk [32 c][128 p] fp32 -> packed bf16x2 hi/lo words ---
#pragma unroll
        for (int i = 0; i < 4; i++) {
            int idx = tid + i * 256;
            int c  = idx >> 5;
            int p4 = (idx & 31) * 4;
            float4 v = *(const float4*)(dwp + (size_t)(ck * 32 + c) * NPIX + p4);

            uint32_t hp0 = bf16x2_rn(v.y, v.x);      // hi(p4+1)<<16 | hi(p4)
            uint32_t hp1 = bf16x2_rn(v.w, v.z);
            float h0 = __uint_as_float(hp0 << 16);
            float h1 = __uint_as_float(hp0 & 0xFFFF0000u);
            float h2 = __uint_as_float(hp1 << 16);
            float h3 = __uint_as_float(hp1 & 0xFFFF0000u);
            uint32_t lp0 = bf16x2_rn(v.y - h1, v.x - h0);
            uint32_t lp1 = bf16x2_rn(v.w - h3, v.z - h2);

            *(uint2*)&Bhs[c * BPAD + p4] = make_uint2(hp0, hp1);
            *(uint2*)&Bls[c * BPAD + p4] = make_uint2(lp0, lp1);
        }
        __syncthreads();

        // --- compute: 2 k16 steps per chunk (EXACT R6/R14) ---
#pragma unroll
        for (int kk = 0; kk < 32; kk += 16) {
            int k0 = kk + q * 2;

            uint32_t bh[4][2], bl[4][2];
#pragma unroll
            for (int nt = 0; nt < 4; nt++) {
                int n = nw + nt * 8 + g;
                bh[nt][0] = (uint32_t)Bhs[k0 * BPAD + n] |
                            ((uint32_t)Bhs[(k0 + 1) * BPAD + n] << 16);
                bh[nt][1] = (uint32_t)Bhs[(k0 + 8) * BPAD + n] |
                            ((uint32_t)Bhs[(k0 + 9) * BPAD + n] << 16);
                bl[nt][0] = (uint32_t)Bls[k0 * BPAD + n] |
                            ((uint32_t)Bls[(k0 + 1) * BPAD + n] << 16);
                bl[nt][1] = (uint32_t)Bls[(k0 + 8) * BPAD + n] |
                            ((uint32_t)Bls[(k0 + 9) * BPAD + n] << 16);
            }

            uint32_t ah[4][4];
#pragma unroll
            for (int mt = 0; mt < 4; mt++) {
                int m = mw + mt * 16 + g;
                ah[mt][0] = *(const uint32_t*)&Ash[m * APAD + k0];
                ah[mt][1] = *(const uint32_t*)&Ash[(m + 8) * APAD + k0];
                ah[mt][2] = *(const uint32_t*)&Ash[m * APAD + k0 + 8];
                ah[mt][3] = *(const uint32_t*)&Ash[(m + 8) * APAD + k0 + 8];
            }

#pragma unroll
            for (int mt = 0; mt < 4; mt++)
#pragma unroll
                for (int nt = 0; nt < 4; nt++)
                    mma_bf16(acc[mt][nt], ah[mt], bh[nt]);

            uint32_t al[4][4];
#pragma unroll
            for (int mt = 0; mt < 4; mt++) {
                int m = mw + mt * 16 + g;
                al[mt][0] = *(const uint32_t*)&Als[m * APAD + k0];
                al[mt][1] = *(const uint32_t*)&Als[(m + 8) * APAD + k0];
                al[mt][2] = *(const uint32_t*)&Als[m * APAD + k0 + 8];
                al[mt][3] = *(const uint32_t*)&Als[(m + 8) * APAD + k0 + 8];
            }
#pragma unroll
            for (int mt = 0; mt < 4; mt++)
#pragma unroll
                for (int nt = 0; nt < 4; nt++)
                    mma_bf16(acc[mt][nt], al[mt], bh[nt]);

#pragma unroll
            for (int mt = 0; mt < 4; mt++)
#pragma unroll
                for (int nt = 0; nt < 4; nt++)
                    mma_bf16(acc[mt][nt], ah[mt], bl[nt]);
        }
    }

    // --- epilogue ---
    float* base = out + (size_t)b * COUT * NPIX + p0;
#pragma unroll
    for (int mt = 0; mt < 4; mt++) {
#pragma unroll
        for (int nt = 0; nt < 4; nt++) {
            int m = mw + mt * 16 + g;
            int n = nw + nt * 8 + q * 2;
            *(float2*)&base[(size_t)m * NPIX + n] =
                make_float2(acc[mt][nt][0], acc[mt][nt][1]);
            *(float2*)&base[(size_t)(m + 8) * NPIX + n] =
                make_float2(acc[mt][nt][2], acc[mt][nt][3]);
        }
    }
}

// ---------------------------------------------------------------------------
// Launch (monolithic, single stream)
// ---------------------------------------------------------------------------
extern "C" void kernel_launch(void* const* d_in, const int* in_sizes, int n_in,
                              void* d_out, int out_size) {
    const float* x   = (const float*)d_in[0];   // [8,256,60,80]
    const float* wdw = (const float*)d_in[1];   // [256,1,3,3]
    const float* wpw = (const float*)d_in[2];   // [128,256]
    float* out = (float*)d_out;                 // [8,128,120,160]

    pwsplit_kernel<<<128, 256>>>(wpw);
    dw_kernel<<<BATCH * CIN, 256>>>(x, wdw);
    gemm_kernel<<<BATCH * (NPIX / 128), 256>>>(out);
}